// round 12
// baseline (speedup 1.0000x reference)
#include <cuda_runtime.h>
#include <cuda_fp16.h>
#include <math.h>

#define NB 128
#define NH 256
#define NW 256
#define NC 64
#define GS 273    // float2 stride per transpose group (16*17 + 1) — conflict-free

// 32 MB static fp16 scratch. W-dimension stored DIGIT-SWAPPED: position
// p = n1*16 + k1 holds spectrum index kw = 16*k1 + n1. Pass 1 writes each
// thread's 16 values contiguously (4x STG.128); pass 3 reads them back
// contiguously (4x LDG.128); pass 2 is per-column agnostic except the mask
// index: column p -> kw = 16*(p&15) + (p>>4).
__device__ __align__(16) __half2 g_scratch[(size_t)NB * NH * NW];

__device__ __forceinline__ float2 cadd(float2 a, float2 b){ return make_float2(a.x+b.x, a.y+b.y); }
__device__ __forceinline__ float2 csub(float2 a, float2 b){ return make_float2(a.x-b.x, a.y-b.y); }
__device__ __forceinline__ float2 cmul(float2 a, float2 b){
    return make_float2(fmaf(a.x, b.x, -a.y*b.y), fmaf(a.x, b.y, a.y*b.x));
}
template<int SIGN>
__device__ __forceinline__ float2 rot90(float2 a){   // × (-i) fwd, (+i) inv
    return (SIGN < 0) ? make_float2(a.y, -a.x) : make_float2(-a.y, a.x);
}
template<int SIGN>
__device__ __forceinline__ float2 cmulw(float2 a, float wr, float wi_f){
    float wi = (SIGN < 0) ? wi_f : -wi_f;
    return make_float2(fmaf(a.x, wr, -a.y*wi), fmaf(a.x, wi, a.y*wr));
}
// scalar (register-safe) pack/unpack: complex float <-> packed half2 in a uint
__device__ __forceinline__ unsigned pk(float2 v){
    __half2 h = __float22half2_rn(v);
    return *reinterpret_cast<unsigned*>(&h);
}
__device__ __forceinline__ float2 upk(unsigned u){
    __half2 h = *reinterpret_cast<__half2*>(&u);
    return __half22float2(h);
}
__device__ __forceinline__ float2 h2f(__half2 v){ return __half22float2(v); }
__device__ __forceinline__ __half2 f2h(float2 v){ return __float22half2_rn(v); }

// Fully-unrolled 16-point DFT in registers, all twiddles as immediates.
template<int SIGN>
__device__ __forceinline__ void fft16(float2* r){
    const float C1 = 0.92387953251f, S1 = 0.38268343236f, C2 = 0.70710678119f;
    float2 v[16];
#pragma unroll
    for (int p = 0; p < 4; ++p){
        float2 a=r[p], b=r[p+4], c=r[p+8], d=r[p+12];
        float2 t0=cadd(a,c), t1=csub(a,c), t2=cadd(b,d);
        float2 t3=rot90<SIGN>(csub(b,d));
        float2 u0=cadd(t0,t2), u1=cadd(t1,t3), u2=csub(t0,t2), u3=csub(t1,t3);
        if (p == 1){
            u1 = cmulw<SIGN>(u1,  C1, -S1);
            u2 = cmulw<SIGN>(u2,  C2, -C2);
            u3 = cmulw<SIGN>(u3,  S1, -C1);
        } else if (p == 2){
            u1 = cmulw<SIGN>(u1,  C2, -C2);
            u2 = rot90<SIGN>(u2);
            u3 = cmulw<SIGN>(u3, -C2, -C2);
        } else if (p == 3){
            u1 = cmulw<SIGN>(u1,  S1, -C1);
            u2 = cmulw<SIGN>(u2, -C2, -C2);
            u3 = cmulw<SIGN>(u3, -C1,  S1);
        }
        v[p]=u0; v[4+p]=u1; v[8+p]=u2; v[12+p]=u3;
    }
#pragma unroll
    for (int m = 0; m < 4; ++m){
        float2 a=v[4*m], b=v[4*m+1], c=v[4*m+2], d=v[4*m+3];
        float2 t0=cadd(a,c), t1=csub(a,c), t2=cadd(b,d);
        float2 t3=rot90<SIGN>(csub(b,d));
        r[m]    = cadd(t0,t2);
        r[4+m]  = cadd(t1,t3);
        r[8+m]  = csub(t0,t2);
        r[12+m] = csub(t1,t3);
    }
}

// r[k] *= w^k, w = exp(SIGN*2*pi*i*n1/256). MUFU base + split even/odd
// power chains (depth ~7 instead of 14, same cmul count).
template<int SIGN>
__device__ __forceinline__ void twiddle_pows(float2* r, int n1){
    float sn, cs;
    __sincosf((float)n1 * 0.024543692606170259f /* pi/128 */, &sn, &cs);
    float2 w1 = make_float2(cs, (SIGN < 0) ? -sn : sn);
    float2 w2 = cmul(w1, w1);
    float2 e = w2;              // even chain: w^2, w^4, ...
    float2 o = cmul(w1, w2);    // odd chain:  w^3, w^5, ...
    r[1] = cmul(r[1], w1);
    r[2] = cmul(r[2], e);
    r[3] = cmul(r[3], o);
#pragma unroll
    for (int k = 2; k < 8; ++k){
        e = cmul(e, w2);
        o = cmul(o, w2);
        r[2*k]   = cmul(r[2*k],   e);
        r[2*k+1] = cmul(r[2*k+1], o);
    }
}

// ---------------------------------------------------------------------------
// Pass 1: forward FFT along W. 16 rows/block, 256 threads. No block barriers.
// Digit-swapped output: 4x STG.128 contiguous per thread.
// ---------------------------------------------------------------------------
__global__ void __launch_bounds__(256) k_rowfft(const float* __restrict__ x){
    __shared__ float2 s[16*GS];
    int t = threadIdx.x;
    int n1 = t & 15, wl = t >> 4;
    int row = blockIdx.x * 16 + wl;
    const float* xr = x + (size_t)row * NW;
    float2 r[16];
#pragma unroll
    for (int n2 = 0; n2 < 16; ++n2) r[n2] = make_float2(xr[n1 + 16*n2], 0.0f);
    fft16<-1>(r);                         // over n2 -> regs k2
    twiddle_pows<-1>(r, n1);
    float2* sg = s + wl*GS;
#pragma unroll
    for (int k2 = 0; k2 < 16; ++k2) sg[n1*17 + k2] = r[k2];
    __syncwarp();
#pragma unroll
    for (int i = 0; i < 16; ++i) r[i] = sg[i*17 + n1];   // thread role: k2 = n1
    fft16<-1>(r);                         // over n1 -> regs k1: X[16*k1 + n1]
    // digit-swapped store: p = n1*16 + k1, scalar-packed into uint4s
    uint4* dst = reinterpret_cast<uint4*>(g_scratch + (size_t)row * NW + n1*16);
    uint4 v0 = make_uint4(pk(r[0]),  pk(r[1]),  pk(r[2]),  pk(r[3]));
    uint4 v1 = make_uint4(pk(r[4]),  pk(r[5]),  pk(r[6]),  pk(r[7]));
    uint4 v2 = make_uint4(pk(r[8]),  pk(r[9]),  pk(r[10]), pk(r[11]));
    uint4 v3 = make_uint4(pk(r[12]), pk(r[13]), pk(r[14]), pk(r[15]));
    dst[0] = v0; dst[1] = v1; dst[2] = v2; dst[3] = v3;
}

// ---------------------------------------------------------------------------
// Pass 2: fwd FFT along H + mask (fftshift folded) + inv FFT along H (×1/256),
// fused, in-place. Block = (batch b, 16-p-column tile). thread: w = t&15,
// u = t>>4. True spectral index of p-column p0+w: kw = 16*w + bx.
// ---------------------------------------------------------------------------
__global__ void __launch_bounds__(256) k_colfft_mask(const float* __restrict__ pi,
                                                     const int* __restrict__ cid){
    __shared__ float2 s[16*GS];
    __shared__ float sPI[NC];
    int t = threadIdx.x;
    int b  = blockIdx.y;
    int bx = blockIdx.x;
    int p0 = bx * 16;
    if (t < NC) sPI[t] = pi[((b + 64) & 127) * NC + t];
    int w = t & 15, u = t >> 4;
    __half2* g = g_scratch + (size_t)b * NH * NW + p0;
    float2 r[16];
#pragma unroll
    for (int n2 = 0; n2 < 16; ++n2) r[n2] = h2f(g[(u + 16*n2)*NW + w]);
    // hoisted cid loads; this column's true spectral index kw = 16*w + bx
    int wp = (16*w + bx + 128) & 255;
    int cc[16];
#pragma unroll
    for (int k1 = 0; k1 < 16; ++k1){
        int hp = (16*k1 + u + 128) & 255;
        cc[k1] = __ldg(&cid[hp*NW + wp]);
    }
    fft16<-1>(r);                         // over n2 -> k2
    twiddle_pows<-1>(r, u);
    float2* sg = s + w*GS;
#pragma unroll
    for (int k2 = 0; k2 < 16; ++k2) sg[u*17 + k2] = r[k2];
    __syncthreads();                      // also covers sPI writes
#pragma unroll
    for (int i = 0; i < 16; ++i) r[i] = sg[i*17 + u];    // thread role: k2 = u
    fft16<-1>(r);                         // over n1 -> k1: F[16*k1 + u]
#pragma unroll
    for (int k1 = 0; k1 < 16; ++k1){
        float m = (cc[k1] < NC) ? sPI[cc[k1]] : 1.0f;
        r[k1].x *= m; r[k1].y *= m;
    }
    fft16<1>(r);                          // over k1 -> m1
    twiddle_pows<1>(r, u);
    __syncthreads();
#pragma unroll
    for (int m1 = 0; m1 < 16; ++m1) sg[u*17 + m1] = r[m1];
    __syncthreads();
#pragma unroll
    for (int i = 0; i < 16; ++i) r[i] = sg[i*17 + u];    // thread role: m1 = u
    fft16<1>(r);                          // over k2 -> m2: y[m1 + 16*m2]
    const float inv256 = 1.0f / 256.0f;
#pragma unroll
    for (int m2 = 0; m2 < 16; ++m2)
        g[(u + 16*m2)*NW + w] = f2h(make_float2(r[m2].x * inv256, r[m2].y * inv256));
}

// ---------------------------------------------------------------------------
// Pass 3: inverse FFT along W (remaining 1/256) + magnitude + 3 channels + pi.
// Digit-swapped scratch: thread u's 16 needed values are contiguous -> 4x LDG.128.
// ---------------------------------------------------------------------------
__global__ void __launch_bounds__(256) k_irow_out(const float* __restrict__ x,
                                                  const float* __restrict__ pi,
                                                  float* __restrict__ out){
    __shared__ float2 s[16*GS];
    int t = threadIdx.x;
    int u = t & 15, rl = t >> 4;
    int row = blockIdx.x * 16 + rl;
    int b = row >> 8, h = row & 255;
    const uint4* srcv = reinterpret_cast<const uint4*>(g_scratch + (size_t)row * NW + u*16);
    uint4 v0 = srcv[0], v1 = srcv[1], v2 = srcv[2], v3 = srcv[3];
    float2 r[16];
    r[0]=upk(v0.x);  r[1]=upk(v0.y);  r[2]=upk(v0.z);  r[3]=upk(v0.w);
    r[4]=upk(v1.x);  r[5]=upk(v1.y);  r[6]=upk(v1.z);  r[7]=upk(v1.w);
    r[8]=upk(v2.x);  r[9]=upk(v2.y);  r[10]=upk(v2.z); r[11]=upk(v2.w);
    r[12]=upk(v3.x); r[13]=upk(v3.y); r[14]=upk(v3.z); r[15]=upk(v3.w);
    fft16<1>(r);                          // over k1 -> m1
    twiddle_pows<1>(r, u);
    float2* sg = s + rl*GS;
#pragma unroll
    for (int m1 = 0; m1 < 16; ++m1) sg[u*17 + m1] = r[m1];
    __syncwarp();
#pragma unroll
    for (int i = 0; i < 16; ++i) r[i] = sg[i*17 + u];    // thread role: m1 = u
    fft16<1>(r);                          // over k2 -> m2: y[u + 16*m2]
    const float sc = 1.0f / 256.0f;       // second half of 1/65536
    const float* xr = x + (size_t)row * NW;
    size_t base = ((size_t)(b*3) * NH + h) * NW;
#pragma unroll
    for (int m2 = 0; m2 < 16; ++m2){
        int m = u + 16*m2;
        float2 v = r[m2];
        float s2 = fmaf(v.x, v.x, v.y*v.y);
        float mag = s2 * __frsqrt_rn(fmaxf(s2, 1e-37f)) * sc;
        float xv = xr[m];
        out[base + m]                      = xv;
        out[base + (size_t)NH*NW + m]      = mag;
        out[base + 2*(size_t)NH*NW + m]    = fabsf(mag - xv);
    }
    if (blockIdx.x == 0){
        for (int i = t; i < NB * NC; i += 256)
            out[(size_t)NB * 3 * NH * NW + i] = pi[i];
    }
}

extern "C" void kernel_launch(void* const* d_in, const int* in_sizes, int n_in,
                              void* d_out, int out_size) {
    const float* x  = (const float*)d_in[0];   // [128,256,256] f32
    const float* pi = (const float*)d_in[1];   // [128,64]      f32
    const int* cid  = (const int*)d_in[2];     // [256,256]     i32
    float* out = (float*)d_out;                // [128,3,256,256] + [128,64]

    k_rowfft<<<(NB*NH)/16, 256>>>(x);
    k_colfft_mask<<<dim3(NW/16, NB), 256>>>(pi, cid);
    k_irow_out<<<(NB*NH)/16, 256>>>(x, pi, out);
}

// round 13
// speedup vs baseline: 1.2194x; 1.2194x over previous
#include <cuda_runtime.h>
#include <cuda_fp16.h>
#include <math.h>

#define NB 128
#define NH 256
#define NW 256
#define NC 64
#define GS 273    // float2 stride per transpose group (16*17 + 1) — conflict-free

// 128*256*256 complex half = 32 MB static scratch (allocation-free)
__device__ __half2 g_scratch[(size_t)NB * NH * NW];

__device__ __forceinline__ float2 cadd(float2 a, float2 b){ return make_float2(a.x+b.x, a.y+b.y); }
__device__ __forceinline__ float2 csub(float2 a, float2 b){ return make_float2(a.x-b.x, a.y-b.y); }
__device__ __forceinline__ float2 cmul(float2 a, float2 b){
    return make_float2(fmaf(a.x, b.x, -a.y*b.y), fmaf(a.x, b.y, a.y*b.x));
}
template<int SIGN>
__device__ __forceinline__ float2 rot90(float2 a){   // × (-i) fwd, (+i) inv
    return (SIGN < 0) ? make_float2(a.y, -a.x) : make_float2(-a.y, a.x);
}
template<int SIGN>
__device__ __forceinline__ float2 cmulw(float2 a, float wr, float wi_f){
    float wi = (SIGN < 0) ? wi_f : -wi_f;
    return make_float2(fmaf(a.x, wr, -a.y*wi), fmaf(a.x, wi, a.y*wr));
}
__device__ __forceinline__ __half2 f2h(float2 v){ return __float22half2_rn(v); }
__device__ __forceinline__ float2 h2f(__half2 v){ return __half22float2(v); }

// Fully-unrolled 16-point DFT in registers, all twiddles as immediates.
template<int SIGN>
__device__ __forceinline__ void fft16(float2* r){
    const float C1 = 0.92387953251f, S1 = 0.38268343236f, C2 = 0.70710678119f;
    float2 v[16];
#pragma unroll
    for (int p = 0; p < 4; ++p){
        float2 a=r[p], b=r[p+4], c=r[p+8], d=r[p+12];
        float2 t0=cadd(a,c), t1=csub(a,c), t2=cadd(b,d);
        float2 t3=rot90<SIGN>(csub(b,d));
        float2 u0=cadd(t0,t2), u1=cadd(t1,t3), u2=csub(t0,t2), u3=csub(t1,t3);
        if (p == 1){
            u1 = cmulw<SIGN>(u1,  C1, -S1);
            u2 = cmulw<SIGN>(u2,  C2, -C2);
            u3 = cmulw<SIGN>(u3,  S1, -C1);
        } else if (p == 2){
            u1 = cmulw<SIGN>(u1,  C2, -C2);
            u2 = rot90<SIGN>(u2);
            u3 = cmulw<SIGN>(u3, -C2, -C2);
        } else if (p == 3){
            u1 = cmulw<SIGN>(u1,  S1, -C1);
            u2 = cmulw<SIGN>(u2, -C2, -C2);
            u3 = cmulw<SIGN>(u3, -C1,  S1);
        }
        v[p]=u0; v[4+p]=u1; v[8+p]=u2; v[12+p]=u3;
    }
#pragma unroll
    for (int m = 0; m < 4; ++m){
        float2 a=v[4*m], b=v[4*m+1], c=v[4*m+2], d=v[4*m+3];
        float2 t0=cadd(a,c), t1=csub(a,c), t2=cadd(b,d);
        float2 t3=rot90<SIGN>(csub(b,d));
        r[m]    = cadd(t0,t2);
        r[4+m]  = cadd(t1,t3);
        r[8+m]  = csub(t0,t2);
        r[12+m] = csub(t1,t3);
    }
}

// r[k] *= w^k, w = exp(SIGN*2*pi*i*n1/256). MUFU base + split even/odd
// power chains (dependency depth ~7 instead of 14, same cmul count).
template<int SIGN>
__device__ __forceinline__ void twiddle_pows(float2* r, int n1){
    float sn, cs;
    __sincosf((float)n1 * 0.024543692606170259f /* pi/128 */, &sn, &cs);
    float2 w1 = make_float2(cs, (SIGN < 0) ? -sn : sn);
    float2 w2 = cmul(w1, w1);
    float2 e = w2;              // even chain: w^2, w^4, ...
    float2 o = cmul(w1, w2);    // odd chain:  w^3, w^5, ...
    r[1] = cmul(r[1], w1);
    r[2] = cmul(r[2], e);
    r[3] = cmul(r[3], o);
#pragma unroll
    for (int k = 2; k < 8; ++k){
        e = cmul(e, w2);
        o = cmul(o, w2);
        r[2*k]   = cmul(r[2*k],   e);
        r[2*k+1] = cmul(r[2*k+1], o);
    }
}

// ---------------------------------------------------------------------------
// Pass 1: forward FFT along W. 16 rows/block, 256 threads. No block barriers.
// ---------------------------------------------------------------------------
__global__ void __launch_bounds__(256) k_rowfft(const float* __restrict__ x){
    __shared__ float2 s[16*GS];
    int t = threadIdx.x;
    int n1 = t & 15, wl = t >> 4;
    int row = blockIdx.x * 16 + wl;
    const float* xr = x + (size_t)row * NW;
    float2 r[16];
#pragma unroll
    for (int n2 = 0; n2 < 16; ++n2) r[n2] = make_float2(xr[n1 + 16*n2], 0.0f);
    fft16<-1>(r);                         // over n2 -> regs k2
    twiddle_pows<-1>(r, n1);
    float2* sg = s + wl*GS;
#pragma unroll
    for (int k2 = 0; k2 < 16; ++k2) sg[n1*17 + k2] = r[k2];
    __syncwarp();
#pragma unroll
    for (int i = 0; i < 16; ++i) r[i] = sg[i*17 + n1];   // thread role: k2 = n1
    fft16<-1>(r);                         // over n1 -> regs k1: X[16*k1 + n1]
    __half2* gp = g_scratch + (size_t)row * NW;
#pragma unroll
    for (int k1 = 0; k1 < 16; ++k1) gp[n1 + 16*k1] = f2h(r[k1]);
}

// ---------------------------------------------------------------------------
// Pass 2: fwd FFT along H + mask (fftshift folded) + inv FFT along H (×1/256),
// fused, in-place. Block = (batch b, 16-column tile). thread: w = t&15, u = t>>4.
// ---------------------------------------------------------------------------
__global__ void __launch_bounds__(256) k_colfft_mask(const float* __restrict__ pi,
                                                     const int* __restrict__ cid){
    __shared__ float2 s[16*GS];
    __shared__ float sPI[NC];
    int t = threadIdx.x;
    int b  = blockIdx.y;
    int w0 = blockIdx.x * 16;
    if (t < NC) sPI[t] = pi[((b + 64) & 127) * NC + t];
    int w = t & 15, u = t >> 4;
    __half2* g = g_scratch + (size_t)b * NH * NW + w0;
    float2 r[16];
#pragma unroll
    for (int n2 = 0; n2 < 16; ++n2) r[n2] = h2f(g[(u + 16*n2)*NW + w]);
    // hoisted cid loads
    int wp = (w0 + w + 128) & 255;
    int cc[16];
#pragma unroll
    for (int k1 = 0; k1 < 16; ++k1){
        int hp = (16*k1 + u + 128) & 255;
        cc[k1] = __ldg(&cid[hp*NW + wp]);
    }
    fft16<-1>(r);                         // over n2 -> k2
    twiddle_pows<-1>(r, u);
    float2* sg = s + w*GS;
#pragma unroll
    for (int k2 = 0; k2 < 16; ++k2) sg[u*17 + k2] = r[k2];
    __syncthreads();                      // also covers sPI writes
#pragma unroll
    for (int i = 0; i < 16; ++i) r[i] = sg[i*17 + u];    // thread role: k2 = u
    fft16<-1>(r);                         // over n1 -> k1: F[16*k1 + u]
#pragma unroll
    for (int k1 = 0; k1 < 16; ++k1){
        float m = (cc[k1] < NC) ? sPI[cc[k1]] : 1.0f;
        r[k1].x *= m; r[k1].y *= m;
    }
    fft16<1>(r);                          // over k1 -> m1
    twiddle_pows<1>(r, u);
    __syncthreads();
#pragma unroll
    for (int m1 = 0; m1 < 16; ++m1) sg[u*17 + m1] = r[m1];
    __syncthreads();
#pragma unroll
    for (int i = 0; i < 16; ++i) r[i] = sg[i*17 + u];    // thread role: m1 = u
    fft16<1>(r);                          // over k2 -> m2: y[m1 + 16*m2]
    const float inv256 = 1.0f / 256.0f;
#pragma unroll
    for (int m2 = 0; m2 < 16; ++m2)
        g[(u + 16*m2)*NW + w] = f2h(make_float2(r[m2].x * inv256, r[m2].y * inv256));
}

// ---------------------------------------------------------------------------
// Pass 3: inverse FFT along W (remaining 1/256) + magnitude + 3 channels + pi.
// ---------------------------------------------------------------------------
__global__ void __launch_bounds__(256) k_irow_out(const float* __restrict__ x,
                                                  const float* __restrict__ pi,
                                                  float* __restrict__ out){
    __shared__ float2 s[16*GS];
    int t = threadIdx.x;
    int u = t & 15, rl = t >> 4;
    int row = blockIdx.x * 16 + rl;
    int b = row >> 8, h = row & 255;
    const __half2* gp = g_scratch + (size_t)row * NW;
    float2 r[16];
#pragma unroll
    for (int k1 = 0; k1 < 16; ++k1) r[k1] = h2f(gp[u + 16*k1]);
    fft16<1>(r);                          // over k1 -> m1
    twiddle_pows<1>(r, u);
    float2* sg = s + rl*GS;
#pragma unroll
    for (int m1 = 0; m1 < 16; ++m1) sg[u*17 + m1] = r[m1];
    __syncwarp();
#pragma unroll
    for (int i = 0; i < 16; ++i) r[i] = sg[i*17 + u];    // thread role: m1 = u
    fft16<1>(r);                          // over k2 -> m2: y[u + 16*m2]
    const float sc = 1.0f / 256.0f;       // second half of 1/65536
    const float* xr = x + (size_t)row * NW;
    size_t base = ((size_t)(b*3) * NH + h) * NW;
#pragma unroll
    for (int m2 = 0; m2 < 16; ++m2){
        int m = u + 16*m2;
        float2 v = r[m2];
        float s2 = fmaf(v.x, v.x, v.y*v.y);
        float mag = s2 * __frsqrt_rn(fmaxf(s2, 1e-37f)) * sc;
        float xv = xr[m];
        out[base + m]                      = xv;
        out[base + (size_t)NH*NW + m]      = mag;
        out[base + 2*(size_t)NH*NW + m]    = fabsf(mag - xv);
    }
    if (blockIdx.x == 0){
        for (int i = t; i < NB * NC; i += 256)
            out[(size_t)NB * 3 * NH * NW + i] = pi[i];
    }
}

extern "C" void kernel_launch(void* const* d_in, const int* in_sizes, int n_in,
                              void* d_out, int out_size) {
    const float* x  = (const float*)d_in[0];   // [128,256,256] f32
    const float* pi = (const float*)d_in[1];   // [128,64]      f32
    const int* cid  = (const int*)d_in[2];     // [256,256]     i32
    float* out = (float*)d_out;                // [128,3,256,256] + [128,64]

    k_rowfft<<<(NB*NH)/16, 256>>>(x);
    k_colfft_mask<<<dim3(NW/16, NB), 256>>>(pi, cid);
    k_irow_out<<<(NB*NH)/16, 256>>>(x, pi, out);
}

// round 14
// speedup vs baseline: 1.2926x; 1.0600x over previous
#include <cuda_runtime.h>
#include <cuda_fp16.h>
#include <math.h>

#define NB 128
#define NH 256
#define NW 256
#define NC 64
#define GS1 272   // 4B-unit group stride, passes 1/3 (≡16 mod 32: complementary banks)
#define GSP 290   // 4B-unit group stride, pass 2    (≡2  mod 32: see derivation)

// 128*256*256 complex half = 32 MB static scratch (allocation-free)
__device__ __half2 g_scratch[(size_t)NB * NH * NW];

__device__ __forceinline__ float2 cadd(float2 a, float2 b){ return make_float2(a.x+b.x, a.y+b.y); }
__device__ __forceinline__ float2 csub(float2 a, float2 b){ return make_float2(a.x-b.x, a.y-b.y); }
__device__ __forceinline__ float2 cmul(float2 a, float2 b){
    return make_float2(fmaf(a.x, b.x, -a.y*b.y), fmaf(a.x, b.y, a.y*b.x));
}
template<int SIGN>
__device__ __forceinline__ float2 rot90(float2 a){   // × (-i) fwd, (+i) inv
    return (SIGN < 0) ? make_float2(a.y, -a.x) : make_float2(-a.y, a.x);
}
template<int SIGN>
__device__ __forceinline__ float2 cmulw(float2 a, float wr, float wi_f){
    float wi = (SIGN < 0) ? wi_f : -wi_f;
    return make_float2(fmaf(a.x, wr, -a.y*wi), fmaf(a.x, wi, a.y*wr));
}
__device__ __forceinline__ __half2 f2h(float2 v){ return __float22half2_rn(v); }
__device__ __forceinline__ float2 h2f(__half2 v){ return __half22float2(v); }
// scalar packed-half2 <-> complex float (register-resident, no arrays)
__device__ __forceinline__ unsigned pk(float2 v){
    __half2 h = __float22half2_rn(v);
    return *reinterpret_cast<unsigned*>(&h);
}
__device__ __forceinline__ float2 upk(unsigned u){
    __half2 h = *reinterpret_cast<__half2*>(&u);
    return __half22float2(h);
}

// Fully-unrolled 16-point DFT in registers, all twiddles as immediates.
template<int SIGN>
__device__ __forceinline__ void fft16(float2* r){
    const float C1 = 0.92387953251f, S1 = 0.38268343236f, C2 = 0.70710678119f;
    float2 v[16];
#pragma unroll
    for (int p = 0; p < 4; ++p){
        float2 a=r[p], b=r[p+4], c=r[p+8], d=r[p+12];
        float2 t0=cadd(a,c), t1=csub(a,c), t2=cadd(b,d);
        float2 t3=rot90<SIGN>(csub(b,d));
        float2 u0=cadd(t0,t2), u1=cadd(t1,t3), u2=csub(t0,t2), u3=csub(t1,t3);
        if (p == 1){
            u1 = cmulw<SIGN>(u1,  C1, -S1);
            u2 = cmulw<SIGN>(u2,  C2, -C2);
            u3 = cmulw<SIGN>(u3,  S1, -C1);
        } else if (p == 2){
            u1 = cmulw<SIGN>(u1,  C2, -C2);
            u2 = rot90<SIGN>(u2);
            u3 = cmulw<SIGN>(u3, -C2, -C2);
        } else if (p == 3){
            u1 = cmulw<SIGN>(u1,  S1, -C1);
            u2 = cmulw<SIGN>(u2, -C2, -C2);
            u3 = cmulw<SIGN>(u3, -C1,  S1);
        }
        v[p]=u0; v[4+p]=u1; v[8+p]=u2; v[12+p]=u3;
    }
#pragma unroll
    for (int m = 0; m < 4; ++m){
        float2 a=v[4*m], b=v[4*m+1], c=v[4*m+2], d=v[4*m+3];
        float2 t0=cadd(a,c), t1=csub(a,c), t2=cadd(b,d);
        float2 t3=rot90<SIGN>(csub(b,d));
        r[m]    = cadd(t0,t2);
        r[4+m]  = cadd(t1,t3);
        r[8+m]  = csub(t0,t2);
        r[12+m] = csub(t1,t3);
    }
}

// r[k] *= w^k, w = exp(SIGN*2*pi*i*n1/256). MUFU base + split even/odd chains.
template<int SIGN>
__device__ __forceinline__ void twiddle_pows(float2* r, int n1){
    float sn, cs;
    __sincosf((float)n1 * 0.024543692606170259f /* pi/128 */, &sn, &cs);
    float2 w1 = make_float2(cs, (SIGN < 0) ? -sn : sn);
    float2 w2 = cmul(w1, w1);
    float2 e = w2;
    float2 o = cmul(w1, w2);
    r[1] = cmul(r[1], w1);
    r[2] = cmul(r[2], e);
    r[3] = cmul(r[3], o);
#pragma unroll
    for (int k = 2; k < 8; ++k){
        e = cmul(e, w2);
        o = cmul(o, w2);
        r[2*k]   = cmul(r[2*k],   e);
        r[2*k+1] = cmul(r[2*k+1], o);
    }
}

// ---------------------------------------------------------------------------
// Pass 1: forward FFT along W. 16 rows/block, 256 threads. fp16 smem transpose.
// ---------------------------------------------------------------------------
__global__ void __launch_bounds__(256) k_rowfft(const float* __restrict__ x){
    __shared__ unsigned s[16*GS1];
    int t = threadIdx.x;
    int n1 = t & 15, wl = t >> 4;
    int row = blockIdx.x * 16 + wl;
    const float* xr = x + (size_t)row * NW;
    float2 r[16];
#pragma unroll
    for (int n2 = 0; n2 < 16; ++n2) r[n2] = make_float2(xr[n1 + 16*n2], 0.0f);
    fft16<-1>(r);                         // over n2 -> regs k2
    twiddle_pows<-1>(r, n1);
    unsigned* sg = s + wl*GS1;
#pragma unroll
    for (int k2 = 0; k2 < 16; ++k2) sg[n1*17 + k2] = pk(r[k2]);
    __syncwarp();
#pragma unroll
    for (int i = 0; i < 16; ++i) r[i] = upk(sg[i*17 + n1]);  // role: k2 = n1
    fft16<-1>(r);                         // over n1 -> regs k1: X[16*k1 + n1]
    __half2* gp = g_scratch + (size_t)row * NW;
#pragma unroll
    for (int k1 = 0; k1 < 16; ++k1) gp[n1 + 16*k1] = f2h(r[k1]);
}

// ---------------------------------------------------------------------------
// Pass 2: fwd FFT along H + mask (fftshift folded, 1/256 folded into mask) +
// inv FFT along H, fused, in-place. fp16 smem transposes (GSP stride).
// ---------------------------------------------------------------------------
__global__ void __launch_bounds__(256) k_colfft_mask(const float* __restrict__ pi,
                                                     const int* __restrict__ cid){
    __shared__ unsigned s[16*GSP];
    __shared__ float sPI[NC];
    int t = threadIdx.x;
    int b  = blockIdx.y;
    int w0 = blockIdx.x * 16;
    const float inv256 = 1.0f / 256.0f;
    if (t < NC) sPI[t] = pi[((b + 64) & 127) * NC + t] * inv256;  // pre-scaled
    int w = t & 15, u = t >> 4;
    __half2* g = g_scratch + (size_t)b * NH * NW + w0;
    float2 r[16];
#pragma unroll
    for (int n2 = 0; n2 < 16; ++n2) r[n2] = h2f(g[(u + 16*n2)*NW + w]);
    // hoisted cid loads
    int wp = (w0 + w + 128) & 255;
    int cc[16];
#pragma unroll
    for (int k1 = 0; k1 < 16; ++k1){
        int hp = (16*k1 + u + 128) & 255;
        cc[k1] = __ldg(&cid[hp*NW + wp]);
    }
    fft16<-1>(r);                         // over n2 -> k2
    twiddle_pows<-1>(r, u);
    unsigned* sg = s + w*GSP;
#pragma unroll
    for (int k2 = 0; k2 < 16; ++k2) sg[u*17 + k2] = pk(r[k2]);
    __syncthreads();                      // also covers sPI writes
#pragma unroll
    for (int i = 0; i < 16; ++i) r[i] = upk(sg[i*17 + u]);   // role: k2 = u
    fft16<-1>(r);                         // over n1 -> k1: F[16*k1 + u]
    // mask (with 1/256 H-normalization folded in): keeps fp16 smem in range
#pragma unroll
    for (int k1 = 0; k1 < 16; ++k1){
        float m = (cc[k1] < NC) ? sPI[cc[k1]] : inv256;
        r[k1].x *= m; r[k1].y *= m;
    }
    fft16<1>(r);                          // over k1 -> m1
    twiddle_pows<1>(r, u);
    __syncthreads();
#pragma unroll
    for (int m1 = 0; m1 < 16; ++m1) sg[u*17 + m1] = pk(r[m1]);
    __syncthreads();
#pragma unroll
    for (int i = 0; i < 16; ++i) r[i] = upk(sg[i*17 + u]);   // role: m1 = u
    fft16<1>(r);                          // over k2 -> m2: y[m1 + 16*m2]
#pragma unroll
    for (int m2 = 0; m2 < 16; ++m2)
        g[(u + 16*m2)*NW + w] = f2h(r[m2]);
}

// ---------------------------------------------------------------------------
// Pass 3: inverse FFT along W (1/256) + magnitude + 3 channels + pi tail.
// fp16 smem transpose (GS1 stride).
// ---------------------------------------------------------------------------
__global__ void __launch_bounds__(256) k_irow_out(const float* __restrict__ x,
                                                  const float* __restrict__ pi,
                                                  float* __restrict__ out){
    __shared__ unsigned s[16*GS1];
    int t = threadIdx.x;
    int u = t & 15, rl = t >> 4;
    int row = blockIdx.x * 16 + rl;
    int b = row >> 8, h = row & 255;
    const __half2* gp = g_scratch + (size_t)row * NW;
    float2 r[16];
#pragma unroll
    for (int k1 = 0; k1 < 16; ++k1) r[k1] = h2f(gp[u + 16*k1]);
    fft16<1>(r);                          // over k1 -> m1
    twiddle_pows<1>(r, u);
    unsigned* sg = s + rl*GS1;
#pragma unroll
    for (int m1 = 0; m1 < 16; ++m1) sg[u*17 + m1] = pk(r[m1]);
    __syncwarp();
#pragma unroll
    for (int i = 0; i < 16; ++i) r[i] = upk(sg[i*17 + u]);   // role: m1 = u
    fft16<1>(r);                          // over k2 -> m2: y[u + 16*m2]
    const float sc = 1.0f / 256.0f;       // W-inverse normalization
    const float* xr = x + (size_t)row * NW;
    size_t base = ((size_t)(b*3) * NH + h) * NW;
#pragma unroll
    for (int m2 = 0; m2 < 16; ++m2){
        int m = u + 16*m2;
        float2 v = r[m2];
        float s2 = fmaf(v.x, v.x, v.y*v.y);
        float mag = s2 * __frsqrt_rn(fmaxf(s2, 1e-37f)) * sc;
        float xv = xr[m];
        out[base + m]                      = xv;
        out[base + (size_t)NH*NW + m]      = mag;
        out[base + 2*(size_t)NH*NW + m]    = fabsf(mag - xv);
    }
    if (blockIdx.x == 0){
        for (int i = t; i < NB * NC; i += 256)
            out[(size_t)NB * 3 * NH * NW + i] = pi[i];
    }
}

extern "C" void kernel_launch(void* const* d_in, const int* in_sizes, int n_in,
                              void* d_out, int out_size) {
    const float* x  = (const float*)d_in[0];   // [128,256,256] f32
    const float* pi = (const float*)d_in[1];   // [128,64]      f32
    const int* cid  = (const int*)d_in[2];     // [256,256]     i32
    float* out = (float*)d_out;                // [128,3,256,256] + [128,64]

    k_rowfft<<<(NB*NH)/16, 256>>>(x);
    k_colfft_mask<<<dim3(NW/16, NB), 256>>>(pi, cid);
    k_irow_out<<<(NB*NH)/16, 256>>>(x, pi, out);
}

// round 15
// speedup vs baseline: 1.2933x; 1.0005x over previous
#include <cuda_runtime.h>
#include <cuda_fp16.h>
#include <math.h>

#define NB 128
#define NH 256
#define NW 256
#define NC 64
#define GS1 272   // 4B-unit group stride, passes 1/3 (≡16 mod 32: complementary banks)
#define GSP 290   // 4B-unit group stride, pass 2    (≡2  mod 32)

// 128*256*256 complex half = 32 MB static scratch (allocation-free)
__device__ __half2 g_scratch[(size_t)NB * NH * NW];

typedef unsigned long long u64c;   // packed complex: lo=re, hi=im (f32x2 lanes)

__device__ __forceinline__ u64c pkc(float x, float y){
    u64c r; asm("mov.b64 %0, {%1, %2};" : "=l"(r) : "f"(x), "f"(y)); return r;
}
__device__ __forceinline__ float2 upc(u64c a){
    float2 v; asm("mov.b64 {%0, %1}, %2;" : "=f"(v.x), "=f"(v.y) : "l"(a)); return v;
}
__device__ __forceinline__ u64c addp(u64c a, u64c b){
    u64c r; asm("add.rn.f32x2 %0, %1, %2;" : "=l"(r) : "l"(a), "l"(b)); return r;
}
__device__ __forceinline__ u64c subp(u64c a, u64c b){
    u64c r; asm("sub.rn.f32x2 %0, %1, %2;" : "=l"(r) : "l"(a), "l"(b)); return r;
}
__device__ __forceinline__ u64c mulp(u64c a, u64c b){
    u64c r; asm("mul.rn.f32x2 %0, %1, %2;" : "=l"(r) : "l"(a), "l"(b)); return r;
}
__device__ __forceinline__ u64c fmap(u64c a, u64c b, u64c c){
    u64c r; asm("fma.rn.f32x2 %0, %1, %2, %3;" : "=l"(r) : "l"(a), "l"(b), "l"(c)); return r;
}
__device__ __forceinline__ u64c swp(u64c a){            // (re,im) -> (im,re)
    float2 v = upc(a); return pkc(v.y, v.x);
}
template<int SIGN>
__device__ __forceinline__ u64c rot90p(u64c a){         // × (-i) fwd, (+i) inv
    float2 v = upc(a);
    return (SIGN < 0) ? pkc(v.y, -v.x) : pkc(-v.y, v.x);
}
// multiply by constant twiddle (forward components wr, wi); conj for inverse
template<int SIGN>
__device__ __forceinline__ u64c cmulwp(u64c a, float wr, float wi_f){
    float wi = (SIGN < 0) ? wi_f : -wi_f;
    return fmap(swp(a), pkc(-wi, wi), mulp(a, pkc(wr, wr)));
}

__device__ __forceinline__ float2 cmul(float2 a, float2 b){
    return make_float2(fmaf(a.x, b.x, -a.y*b.y), fmaf(a.x, b.y, a.y*b.x));
}
__device__ __forceinline__ __half2 f2h(float2 v){ return __float22half2_rn(v); }
__device__ __forceinline__ float2 h2f(__half2 v){ return __half22float2(v); }
__device__ __forceinline__ unsigned pk(float2 v){
    __half2 h = __float22half2_rn(v);
    return *reinterpret_cast<unsigned*>(&h);
}
__device__ __forceinline__ float2 upk(unsigned u){
    __half2 h = *reinterpret_cast<__half2*>(&u);
    return __half22float2(h);
}

// Fully-unrolled 16-point DFT, butterflies in packed f32x2, natural order.
template<int SIGN>
__device__ __forceinline__ void fft16(float2* rf){
    const float C1 = 0.92387953251f, S1 = 0.38268343236f, C2 = 0.70710678119f;
    u64c r[16];
#pragma unroll
    for (int i = 0; i < 16; ++i) r[i] = pkc(rf[i].x, rf[i].y);
    u64c v[16];
#pragma unroll
    for (int p = 0; p < 4; ++p){
        u64c a=r[p], b=r[p+4], c=r[p+8], d=r[p+12];
        u64c t0=addp(a,c), t1=subp(a,c), t2=addp(b,d);
        u64c t3=rot90p<SIGN>(subp(b,d));
        u64c u0=addp(t0,t2), u1=addp(t1,t3), u2=subp(t0,t2), u3=subp(t1,t3);
        if (p == 1){
            u1 = cmulwp<SIGN>(u1,  C1, -S1);
            u2 = cmulwp<SIGN>(u2,  C2, -C2);
            u3 = cmulwp<SIGN>(u3,  S1, -C1);
        } else if (p == 2){
            u1 = cmulwp<SIGN>(u1,  C2, -C2);
            u2 = rot90p<SIGN>(u2);
            u3 = cmulwp<SIGN>(u3, -C2, -C2);
        } else if (p == 3){
            u1 = cmulwp<SIGN>(u1,  S1, -C1);
            u2 = cmulwp<SIGN>(u2, -C2, -C2);
            u3 = cmulwp<SIGN>(u3, -C1,  S1);
        }
        v[p]=u0; v[4+p]=u1; v[8+p]=u2; v[12+p]=u3;
    }
#pragma unroll
    for (int m = 0; m < 4; ++m){
        u64c a=v[4*m], b=v[4*m+1], c=v[4*m+2], d=v[4*m+3];
        u64c t0=addp(a,c), t1=subp(a,c), t2=addp(b,d);
        u64c t3=rot90p<SIGN>(subp(b,d));
        r[m]    = addp(t0,t2);
        r[4+m]  = addp(t1,t3);
        r[8+m]  = subp(t0,t2);
        r[12+m] = subp(t1,t3);
    }
#pragma unroll
    for (int i = 0; i < 16; ++i) rf[i] = upc(r[i]);
}

// r[k] *= w^k, w = exp(SIGN*2*pi*i*n1/256). MUFU base + split even/odd chains.
template<int SIGN>
__device__ __forceinline__ void twiddle_pows(float2* r, int n1){
    float sn, cs;
    __sincosf((float)n1 * 0.024543692606170259f /* pi/128 */, &sn, &cs);
    float2 w1 = make_float2(cs, (SIGN < 0) ? -sn : sn);
    float2 w2 = cmul(w1, w1);
    float2 e = w2;
    float2 o = cmul(w1, w2);
    r[1] = cmul(r[1], w1);
    r[2] = cmul(r[2], e);
    r[3] = cmul(r[3], o);
#pragma unroll
    for (int k = 2; k < 8; ++k){
        e = cmul(e, w2);
        o = cmul(o, w2);
        r[2*k]   = cmul(r[2*k],   e);
        r[2*k+1] = cmul(r[2*k+1], o);
    }
}

// ---------------------------------------------------------------------------
// Pass 1: forward FFT along W. 16 rows/block, 256 threads. fp16 smem transpose.
// ---------------------------------------------------------------------------
__global__ void __launch_bounds__(256) k_rowfft(const float* __restrict__ x){
    __shared__ unsigned s[16*GS1];
    int t = threadIdx.x;
    int n1 = t & 15, wl = t >> 4;
    int row = blockIdx.x * 16 + wl;
    const float* xr = x + (size_t)row * NW;
    float2 r[16];
#pragma unroll
    for (int n2 = 0; n2 < 16; ++n2) r[n2] = make_float2(xr[n1 + 16*n2], 0.0f);
    fft16<-1>(r);                         // over n2 -> regs k2
    twiddle_pows<-1>(r, n1);
    unsigned* sg = s + wl*GS1;
#pragma unroll
    for (int k2 = 0; k2 < 16; ++k2) sg[n1*17 + k2] = pk(r[k2]);
    __syncwarp();
#pragma unroll
    for (int i = 0; i < 16; ++i) r[i] = upk(sg[i*17 + n1]);  // role: k2 = n1
    fft16<-1>(r);                         // over n1 -> regs k1: X[16*k1 + n1]
    __half2* gp = g_scratch + (size_t)row * NW;
#pragma unroll
    for (int k1 = 0; k1 < 16; ++k1) gp[n1 + 16*k1] = f2h(r[k1]);
}

// ---------------------------------------------------------------------------
// Pass 2: fwd FFT along H + mask (fftshift folded, 1/256 folded into mask) +
// inv FFT along H, fused, in-place. fp16 smem transposes (GSP stride).
// ---------------------------------------------------------------------------
__global__ void __launch_bounds__(256) k_colfft_mask(const float* __restrict__ pi,
                                                     const int* __restrict__ cid){
    __shared__ unsigned s[16*GSP];
    __shared__ float sPI[NC];
    int t = threadIdx.x;
    int b  = blockIdx.y;
    int w0 = blockIdx.x * 16;
    const float inv256 = 1.0f / 256.0f;
    if (t < NC) sPI[t] = pi[((b + 64) & 127) * NC + t] * inv256;  // pre-scaled
    int w = t & 15, u = t >> 4;
    __half2* g = g_scratch + (size_t)b * NH * NW + w0;
    float2 r[16];
#pragma unroll
    for (int n2 = 0; n2 < 16; ++n2) r[n2] = h2f(g[(u + 16*n2)*NW + w]);
    // hoisted cid loads
    int wp = (w0 + w + 128) & 255;
    int cc[16];
#pragma unroll
    for (int k1 = 0; k1 < 16; ++k1){
        int hp = (16*k1 + u + 128) & 255;
        cc[k1] = __ldg(&cid[hp*NW + wp]);
    }
    fft16<-1>(r);                         // over n2 -> k2
    twiddle_pows<-1>(r, u);
    unsigned* sg = s + w*GSP;
#pragma unroll
    for (int k2 = 0; k2 < 16; ++k2) sg[u*17 + k2] = pk(r[k2]);
    __syncthreads();                      // also covers sPI writes
#pragma unroll
    for (int i = 0; i < 16; ++i) r[i] = upk(sg[i*17 + u]);   // role: k2 = u
    fft16<-1>(r);                         // over n1 -> k1: F[16*k1 + u]
    // mask (1/256 H-normalization folded in): keeps fp16 smem in range
#pragma unroll
    for (int k1 = 0; k1 < 16; ++k1){
        float m = (cc[k1] < NC) ? sPI[cc[k1]] : inv256;
        r[k1].x *= m; r[k1].y *= m;
    }
    fft16<1>(r);                          // over k1 -> m1
    twiddle_pows<1>(r, u);
    __syncthreads();
#pragma unroll
    for (int m1 = 0; m1 < 16; ++m1) sg[u*17 + m1] = pk(r[m1]);
    __syncthreads();
#pragma unroll
    for (int i = 0; i < 16; ++i) r[i] = upk(sg[i*17 + u]);   // role: m1 = u
    fft16<1>(r);                          // over k2 -> m2: y[m1 + 16*m2]
#pragma unroll
    for (int m2 = 0; m2 < 16; ++m2)
        g[(u + 16*m2)*NW + w] = f2h(r[m2]);
}

// ---------------------------------------------------------------------------
// Pass 3: inverse FFT along W (1/256) + magnitude + 3 channels + pi tail.
// fp16 smem transpose (GS1 stride).
// ---------------------------------------------------------------------------
__global__ void __launch_bounds__(256) k_irow_out(const float* __restrict__ x,
                                                  const float* __restrict__ pi,
                                                  float* __restrict__ out){
    __shared__ unsigned s[16*GS1];
    int t = threadIdx.x;
    int u = t & 15, rl = t >> 4;
    int row = blockIdx.x * 16 + rl;
    int b = row >> 8, h = row & 255;
    const __half2* gp = g_scratch + (size_t)row * NW;
    float2 r[16];
#pragma unroll
    for (int k1 = 0; k1 < 16; ++k1) r[k1] = h2f(gp[u + 16*k1]);
    fft16<1>(r);                          // over k1 -> m1
    twiddle_pows<1>(r, u);
    unsigned* sg = s + rl*GS1;
#pragma unroll
    for (int m1 = 0; m1 < 16; ++m1) sg[u*17 + m1] = pk(r[m1]);
    __syncwarp();
#pragma unroll
    for (int i = 0; i < 16; ++i) r[i] = upk(sg[i*17 + u]);   // role: m1 = u
    fft16<1>(r);                          // over k2 -> m2: y[u + 16*m2]
    const float sc = 1.0f / 256.0f;       // W-inverse normalization
    const float* xr = x + (size_t)row * NW;
    size_t base = ((size_t)(b*3) * NH + h) * NW;
#pragma unroll
    for (int m2 = 0; m2 < 16; ++m2){
        int m = u + 16*m2;
        float2 v = r[m2];
        float s2 = fmaf(v.x, v.x, v.y*v.y);
        float mag = s2 * __frsqrt_rn(fmaxf(s2, 1e-37f)) * sc;
        float xv = xr[m];
        out[base + m]                      = xv;
        out[base + (size_t)NH*NW + m]      = mag;
        out[base + 2*(size_t)NH*NW + m]    = fabsf(mag - xv);
    }
    if (blockIdx.x == 0){
        for (int i = t; i < NB * NC; i += 256)
            out[(size_t)NB * 3 * NH * NW + i] = pi[i];
    }
}

extern "C" void kernel_launch(void* const* d_in, const int* in_sizes, int n_in,
                              void* d_out, int out_size) {
    const float* x  = (const float*)d_in[0];   // [128,256,256] f32
    const float* pi = (const float*)d_in[1];   // [128,64]      f32
    const int* cid  = (const int*)d_in[2];     // [256,256]     i32
    float* out = (float*)d_out;                // [128,3,256,256] + [128,64]

    k_rowfft<<<(NB*NH)/16, 256>>>(x);
    k_colfft_mask<<<dim3(NW/16, NB), 256>>>(pi, cid);
    k_irow_out<<<(NB*NH)/16, 256>>>(x, pi, out);
}